// round 11
// baseline (speedup 1.0000x reference)
#include <cuda_runtime.h>
#include <cuda_fp16.h>
#include <cstdint>
#include <math.h>

// ---------------- problem constants ----------------
#define BB 2048
#define KK 2048
#define HH 2048
#define FH 8192

// ---------------- quantization scales ----------------
#define SA_F (6.0f/16256.0f)
#define SW_F (0.14f/16256.0f)
#define QA_MUL (16256.0f/6.0f)
#define QW_MUL (16256.0f/0.14f)
#define C1_F (SA_F*SW_F*16384.0f)   // gate = C1*(P1 + P2/128)
#define INV128 0.0078125f

// ---------------- GEMM config ----------------
#define BM 64
#define BN 128             // 4 gates x 32 h
#define BK 64              // int8 K elems per chunk; hi|lo packed in 128B row
#define NTH 256            // 8 warps: 2 (M) x 4 (N)
#define NCHUNK 64          // 2 phases * (2048/64)
#define ROWB 128           // [hi 64B | lo 64B]
#define OFF_W 8192         // W tile offset within stage (A = 64*128B = 8KB)
#define STAGE_BYTES 24576  // A 8K + W 16K
#define NSTAGE 4
#define SMEM_TOTAL (NSTAGE*STAGE_BYTES)   // 96 KB; 2 CTAs/SM
#define EPI_STRIDE 132

// ---------------- scratch ----------------
__device__ __align__(16) signed char g_qah[2][(size_t)BB*KK];
__device__ __align__(16) signed char g_qal[2][(size_t)BB*KK];
__device__ __align__(16) signed char g_qwh[2][(size_t)FH*KK];
__device__ __align__(16) signed char g_qwl[2][(size_t)FH*KK];

// ---------------- PTX helpers ----------------
__device__ __forceinline__ uint32_t smem_u32(const void* p) {
    return (uint32_t)__cvta_generic_to_shared(p);
}
__device__ __forceinline__ void cp16(uint32_t s, const void* g) {
    asm volatile("cp.async.cg.shared.global [%0], [%1], 16;"
                 :: "r"(s), "l"(__cvta_generic_to_global(g)) : "memory");
}
__device__ __forceinline__ void cp_commit() {
    asm volatile("cp.async.commit_group;" ::: "memory");
}
template <int N>
__device__ __forceinline__ void cp_wait() {
    asm volatile("cp.async.wait_group %0;" :: "n"(N) : "memory");
}
__device__ __forceinline__ void ldsm4(uint32_t* r, uint32_t a) {
    asm volatile("ldmatrix.sync.aligned.m8n8.x4.shared.b16 {%0,%1,%2,%3}, [%4];"
                 : "=r"(r[0]), "=r"(r[1]), "=r"(r[2]), "=r"(r[3]) : "r"(a));
}
__device__ __forceinline__ void mma_s8(int* c, const uint32_t* a, const uint32_t* b) {
    asm volatile(
        "mma.sync.aligned.m16n8k32.row.col.s32.s8.s8.s32 "
        "{%0,%1,%2,%3}, {%4,%5,%6,%7}, {%8,%9}, {%0,%1,%2,%3};"
        : "+r"(c[0]), "+r"(c[1]), "+r"(c[2]), "+r"(c[3])
        : "r"(a[0]), "r"(a[1]), "r"(a[2]), "r"(a[3]), "r"(b[0]), "r"(b[1]));
}
__device__ __forceinline__ uint32_t swz(uint32_t x) {   // SW128
    return x ^ ((x >> 3) & 0x70);
}
__device__ __forceinline__ float sigmoidf_(float v) { return 1.0f / (1.0f + expf(-v)); }

// ---------------- one fused quant launch for all four tensors ----------------
#define QB_A 1024
#define QB_W 4096
__global__ void quant_all(const float4* __restrict__ x,
                          const float4* __restrict__ h,
                          const float4* __restrict__ wih,
                          const float4* __restrict__ whh,
                          uint4* __restrict__ qah, uint4* __restrict__ qal,
                          uint4* __restrict__ qwh, uint4* __restrict__ qwl)
{
    const int b = blockIdx.x;
    const float4* src;
    uint4 *qh, *ql;
    float qmul;
    int i;
    const int A16 = BB * KK / 16;
    const int W16 = FH * KK / 16;

    if (b < QB_A) {
        src = x;  qh = qah;  ql = qal;  qmul = QA_MUL;
        i = b * 256 + threadIdx.x;           if (i >= A16) return;
    } else if (b < 2 * QB_A) {
        src = h;  qh = qah + A16;  ql = qal + A16;  qmul = QA_MUL;
        i = (b - QB_A) * 256 + threadIdx.x;  if (i >= A16) return;
    } else if (b < 2 * QB_A + QB_W) {
        src = wih;  qh = qwh;  ql = qwl;  qmul = QW_MUL;
        i = (b - 2 * QB_A) * 256 + threadIdx.x;        if (i >= W16) return;
    } else {
        src = whh;  qh = qwh + W16;  ql = qwl + W16;  qmul = QW_MUL;
        i = (b - 2 * QB_A - QB_W) * 256 + threadIdx.x; if (i >= W16) return;
    }

    float4 v[4];
    v[0] = src[4 * i];
    v[1] = src[4 * i + 1];
    v[2] = src[4 * i + 2];
    v[3] = src[4 * i + 3];
    union { uint4 u; signed char c[16]; } H, L;
    const float* f = (const float*)v;
    #pragma unroll
    for (int k = 0; k < 16; ++k) {
        int q = __float2int_rn(f[k] * qmul);
        q = max(-16256, min(16256, q));
        int hq = (q + 64) >> 7;
        int lq = q - (hq << 7);
        H.c[k] = (signed char)hq;
        L.c[k] = (signed char)lq;
    }
    qh[i] = H.u;
    ql[i] = L.u;
}

// ---------------- tile loader: K64 chunk; rows = [hi 64B | lo 64B] ----------
__device__ __forceinline__ void load_chunk(int c, uint32_t stage, int m0, int hb, int tid)
{
    const int ph = c >> 5;
    const int k0 = (c & 31) * BK;
    const signed char* __restrict__ Ah = g_qah[ph];
    const signed char* __restrict__ Al = g_qal[ph];
    const signed char* __restrict__ Wh = g_qwh[ph];
    const signed char* __restrict__ Wl = g_qwl[ph];

    #pragma unroll
    for (int j = 0; j < 2; ++j) {          // A: 64 rows x 8 x 16B
        int idx = tid + j * NTH;
        int r = idx >> 3, cb = idx & 7;
        uint32_t so = swz((uint32_t)(r * ROWB + cb * 16));
        size_t go = (size_t)(m0 + r) * KK + k0 + (cb & 3) * 16;
        cp16(stage + so, (cb < 4) ? (Ah + go) : (Al + go));
    }
    #pragma unroll
    for (int j = 0; j < 4; ++j) {          // W: 128 rows x 8 x 16B
        int idx = tid + j * NTH;
        int r = idx >> 3, cb = idx & 7;
        uint32_t so = swz((uint32_t)(r * ROWB + cb * 16));
        int wrow = ((r >> 5) << 11) + hb + (r & 31);   // gate*2048 + hb + h
        size_t go = (size_t)wrow * KK + k0 + (cb & 3) * 16;
        cp16(stage + OFF_W + so, (cb < 4) ? (Wh + go) : (Wl + go));
    }
}

// ---------------- int8 3-product GEMM + fused LSTM epilogue ----------------
__global__ __launch_bounds__(NTH, 2)
void lstm_gemm_fused(const float* __restrict__ Cprev,
                     const float* __restrict__ bih,
                     const float* __restrict__ bhh,
                     float* __restrict__ out)
{
    extern __shared__ __align__(1024) char smem[];
    const uint32_t sb = smem_u32(smem);
    const int tid = threadIdx.x;
    const int wid = tid >> 5;
    const int l   = tid & 31;
    const int m0  = blockIdx.y * BM;
    const int hb  = blockIdx.x * 32;
    const int wm  = wid & 1;
    const int wn  = wid >> 1;

    int acc1[2][4][4], acc2[2][4][4];
    #pragma unroll
    for (int mt = 0; mt < 2; ++mt)
        #pragma unroll
        for (int nt = 0; nt < 4; ++nt)
            #pragma unroll
            for (int q = 0; q < 4; ++q) { acc1[mt][nt][q] = 0; acc2[mt][nt][q] = 0; }

    // hi at col [0,64), lo = hi ^ 64; k-step (+32) = ^32.  Bits 5,6 don't feed
    // the SW128 mask and base col bits are clear -> XOR == add after swizzle.
    uint32_t swzA[2];
    #pragma unroll
    for (int mt = 0; mt < 2; ++mt) {
        int r = wm * 32 + mt * 16 + (l & 15);
        swzA[mt] = swz((uint32_t)(r * ROWB + (l >> 4) * 16));
    }
    uint32_t swzB[2];
    #pragma unroll
    for (int np = 0; np < 2; ++np) {
        int r = wn * 32 + np * 16 + ((l >> 4) << 3) + (l & 7);
        swzB[np] = swz((uint32_t)(r * ROWB + ((l >> 3) & 1) * 16));
    }

    // prologue: 3 chunks in flight
    load_chunk(0, sb, m0, hb, tid);
    cp_commit();
    load_chunk(1, sb + STAGE_BYTES, m0, hb, tid);
    cp_commit();
    load_chunk(2, sb + 2 * STAGE_BYTES, m0, hb, tid);
    cp_commit();

    for (int c = 0; c < NCHUNK; ++c) {
        const uint32_t base = sb + (uint32_t)(c % NSTAGE) * STAGE_BYTES;

        cp_wait<2>();            // chunk c resident (c+1, c+2 in flight)
        __syncthreads();         // all warps done with stage (c-1)%4

        // Issue next load FIRST: flight covered by 3 chunks of compute.
        if (c + 3 < NCHUNK)
            load_chunk(c + 3, sb + (uint32_t)((c + 3) % NSTAGE) * STAGE_BYTES,
                       m0, hb, tid);
        cp_commit();

        #pragma unroll
        for (int ks = 0; ks < 2; ++ks) {
            const uint32_t kx = (uint32_t)ks << 5;
            uint32_t bh[2][4], bl[2][4];
            #pragma unroll
            for (int np = 0; np < 2; ++np) {
                ldsm4(bh[np], base + OFF_W + (swzB[np] ^ kx));
                ldsm4(bl[np], base + OFF_W + (swzB[np] ^ kx ^ 64));
            }
            uint32_t ah[2][4], al[2][4];
            #pragma unroll
            for (int mt = 0; mt < 2; ++mt) {
                ldsm4(ah[mt], base + (swzA[mt] ^ kx));
                ldsm4(al[mt], base + (swzA[mt] ^ kx ^ 64));
            }
            #pragma unroll
            for (int mt = 0; mt < 2; ++mt) {
                #pragma unroll
                for (int nt = 0; nt < 4; ++nt)
                    mma_s8(acc1[mt][nt], ah[mt], &bh[nt >> 1][(nt & 1) * 2]);
                #pragma unroll
                for (int nt = 0; nt < 4; ++nt)
                    mma_s8(acc2[mt][nt], ah[mt], &bl[nt >> 1][(nt & 1) * 2]);
                #pragma unroll
                for (int nt = 0; nt < 4; ++nt)
                    mma_s8(acc2[mt][nt], al[mt], &bh[nt >> 1][(nt & 1) * 2]);
            }
        }
    }

    // ---- fused epilogue ----
    __syncthreads();
    float* sg = (float*)smem;              // [64][EPI_STRIDE] f32 gate tile

    const int rb = wm * 32 + (l >> 2);
    const int cb = wn * 32 + 2 * (l & 3);
    #pragma unroll
    for (int mt = 0; mt < 2; ++mt) {
        #pragma unroll
        for (int nt = 0; nt < 4; ++nt) {
            const int r = rb + mt * 16;
            const int cc = cb + nt * 8;
            float g0 = C1_F * fmaf(INV128, (float)acc2[mt][nt][0], (float)acc1[mt][nt][0]);
            float g1 = C1_F * fmaf(INV128, (float)acc2[mt][nt][1], (float)acc1[mt][nt][1]);
            float g2 = C1_F * fmaf(INV128, (float)acc2[mt][nt][2], (float)acc1[mt][nt][2]);
            float g3 = C1_F * fmaf(INV128, (float)acc2[mt][nt][3], (float)acc1[mt][nt][3]);
            sg[r * EPI_STRIDE + cc]           = g0;
            sg[r * EPI_STRIDE + cc + 1]       = g1;
            sg[(r + 8) * EPI_STRIDE + cc]     = g2;
            sg[(r + 8) * EPI_STRIDE + cc + 1] = g3;
        }
    }
    __syncthreads();

    const int hh = (tid & 7) * 4;
    const int H = hb + hh;
    float4 bI, bF, bG, bO;
    {
        float4 a0 = *(const float4*)(bih + H);
        float4 a1 = *(const float4*)(bhh + H);
        bI = make_float4(a0.x + a1.x, a0.y + a1.y, a0.z + a1.z, a0.w + a1.w);
        a0 = *(const float4*)(bih + HH + H);
        a1 = *(const float4*)(bhh + HH + H);
        bF = make_float4(a0.x + a1.x, a0.y + a1.y, a0.z + a1.z, a0.w + a1.w);
        a0 = *(const float4*)(bih + 2 * HH + H);
        a1 = *(const float4*)(bhh + 2 * HH + H);
        bG = make_float4(a0.x + a1.x, a0.y + a1.y, a0.z + a1.z, a0.w + a1.w);
        a0 = *(const float4*)(bih + 3 * HH + H);
        a1 = *(const float4*)(bhh + 3 * HH + H);
        bO = make_float4(a0.x + a1.x, a0.y + a1.y, a0.z + a1.z, a0.w + a1.w);
    }
    const size_t S = (size_t)BB * HH;

    for (int mr = tid >> 3; mr < BM; mr += 32) {
        const float* row = sg + mr * EPI_STRIDE;
        float4 gi = *(const float4*)(row + hh);
        float4 gf = *(const float4*)(row + 32 + hh);
        float4 gg = *(const float4*)(row + 64 + hh);
        float4 go = *(const float4*)(row + 96 + hh);
        const size_t gidx = (size_t)(m0 + mr) * HH + H;
        float4 C = *(const float4*)(Cprev + gidx);

        float4 vh, vC, vf, vi, vg, vo;
        const float* pgi = &gi.x; const float* pgf = &gf.x;
        const float* pgg = &gg.x; const float* pgo = &go.x;
        const float* pbI = &bI.x; const float* pbF = &bF.x;
        const float* pbG = &bG.x; const float* pbO = &bO.x;
        const float* pC = &C.x;
        float* ph = &vh.x; float* pc = &vC.x; float* pf = &vf.x;
        float* pi = &vi.x; float* pg = &vg.x; float* po = &vo.x;
        #pragma unroll
        for (int q = 0; q < 4; ++q) {
            float ig = sigmoidf_(pgi[q] + pbI[q]);
            float fg = sigmoidf_(pgf[q] + pbF[q]);
            float cg = tanhf(pgg[q] + pbG[q]);
            float og = sigmoidf_(pgo[q] + pbO[q]);
            float nC = fg * pC[q] + ig * cg;
            pf[q] = fg; pi[q] = ig; pg[q] = cg; po[q] = og;
            pc[q] = nC;
            ph[q] = og * tanhf(nC);
        }
        *(float4*)(out + gidx)         = vh;
        *(float4*)(out + S + gidx)     = vC;
        *(float4*)(out + 2 * S + gidx) = vf;
        *(float4*)(out + 3 * S + gidx) = vi;
        *(float4*)(out + 4 * S + gidx) = vg;
        *(float4*)(out + 5 * S + gidx) = vo;
    }
}

// ---------------- launch ----------------
extern "C" void kernel_launch(void* const* d_in, const int* in_sizes, int n_in,
                              void* d_out, int out_size)
{
    const float* x     = (const float*)d_in[0];
    const float* hprev = (const float*)d_in[1];
    const float* Cprev = (const float*)d_in[2];
    const float* Wih   = (const float*)d_in[3];
    const float* bih   = (const float*)d_in[4];
    const float* Whh   = (const float*)d_in[5];
    const float* bhh   = (const float*)d_in[6];
    float* out = (float*)d_out;

    signed char *qah, *qal, *qwh, *qwl;
    cudaGetSymbolAddress((void**)&qah, g_qah);
    cudaGetSymbolAddress((void**)&qal, g_qal);
    cudaGetSymbolAddress((void**)&qwh, g_qwh);
    cudaGetSymbolAddress((void**)&qwl, g_qwl);

    static bool attr_set = false;
    if (!attr_set) {
        cudaFuncSetAttribute(lstm_gemm_fused,
                             cudaFuncAttributeMaxDynamicSharedMemorySize, SMEM_TOTAL);
        attr_set = true;
    }

    quant_all<<<2 * QB_A + 2 * QB_W, 256>>>(
        (const float4*)x, (const float4*)hprev,
        (const float4*)Wih, (const float4*)Whh,
        (uint4*)qah, (uint4*)qal, (uint4*)qwh, (uint4*)qwl);

    dim3 grid(FH / BN, BB / BM);   // (64, 32)
    lstm_gemm_fused<<<grid, NTH, SMEM_TOTAL>>>(Cprev, bih, bhh, out);
}

// round 12
// speedup vs baseline: 1.0442x; 1.0442x over previous
#include <cuda_runtime.h>
#include <cuda_fp16.h>
#include <cstdint>
#include <math.h>

// ---------------- problem constants ----------------
#define BB 2048
#define KK 2048
#define HH 2048
#define FH 8192

// ---------------- quantization scales ----------------
#define SA_F (6.0f/16256.0f)
#define SW_F (0.14f/16256.0f)
#define QA_MUL (16256.0f/6.0f)
#define QW_MUL (16256.0f/0.14f)
#define C1_F (SA_F*SW_F*16384.0f)   // gate = C1*(P1 + P2/128)
#define INV128 0.0078125f

// ---------------- GEMM config ----------------
#define BM 128
#define BN 128             // 4 gates x 32 h
#define BK 128
#define NTH 512            // 16 warps: 4 (M) x 4 (N); 1 CTA/SM
#define NCHUNK 32          // 2 phases * (2048/128)
#define ROWB 128
#define OFF_AL 16384
#define OFF_WH 32768
#define OFF_WL 49152
#define STAGE_BYTES 65536
#define NSTAGE 3
#define SMEM_TOTAL (NSTAGE*STAGE_BYTES)   // 192 KB
#define EPI_STRIDE 132

// ---------------- scratch ----------------
__device__ __align__(16) signed char g_qah[2][(size_t)BB*KK];
__device__ __align__(16) signed char g_qal[2][(size_t)BB*KK];
__device__ __align__(16) signed char g_qwh[2][(size_t)FH*KK];
__device__ __align__(16) signed char g_qwl[2][(size_t)FH*KK];

// ---------------- PTX helpers ----------------
__device__ __forceinline__ uint32_t smem_u32(const void* p) {
    return (uint32_t)__cvta_generic_to_shared(p);
}
__device__ __forceinline__ void cp16(uint32_t s, const void* g) {
    asm volatile("cp.async.cg.shared.global [%0], [%1], 16;"
                 :: "r"(s), "l"(__cvta_generic_to_global(g)) : "memory");
}
__device__ __forceinline__ void cp_commit() {
    asm volatile("cp.async.commit_group;" ::: "memory");
}
template <int N>
__device__ __forceinline__ void cp_wait() {
    asm volatile("cp.async.wait_group %0;" :: "n"(N) : "memory");
}
__device__ __forceinline__ void ldsm4(uint32_t* r, uint32_t a) {
    asm volatile("ldmatrix.sync.aligned.m8n8.x4.shared.b16 {%0,%1,%2,%3}, [%4];"
                 : "=r"(r[0]), "=r"(r[1]), "=r"(r[2]), "=r"(r[3]) : "r"(a));
}
__device__ __forceinline__ void mma_s8(int* c, const uint32_t* a, const uint32_t* b) {
    asm volatile(
        "mma.sync.aligned.m16n8k32.row.col.s32.s8.s8.s32 "
        "{%0,%1,%2,%3}, {%4,%5,%6,%7}, {%8,%9}, {%0,%1,%2,%3};"
        : "+r"(c[0]), "+r"(c[1]), "+r"(c[2]), "+r"(c[3])
        : "r"(a[0]), "r"(a[1]), "r"(a[2]), "r"(a[3]), "r"(b[0]), "r"(b[1]));
}
__device__ __forceinline__ uint32_t swz(uint32_t x) {   // SW128
    return x ^ ((x >> 3) & 0x70);
}
__device__ __forceinline__ float sigmoidf_(float v) { return 1.0f / (1.0f + expf(-v)); }

// ---------------- one fused quant launch for all four tensors ----------------
#define QB_A 1024
#define QB_W 4096
__global__ void quant_all(const float4* __restrict__ x,
                          const float4* __restrict__ h,
                          const float4* __restrict__ wih,
                          const float4* __restrict__ whh,
                          uint4* __restrict__ qah, uint4* __restrict__ qal,
                          uint4* __restrict__ qwh, uint4* __restrict__ qwl)
{
    const int b = blockIdx.x;
    const float4* src;
    uint4 *qh, *ql;
    float qmul;
    int i;
    const int A16 = BB * KK / 16;
    const int W16 = FH * KK / 16;

    if (b < QB_A) {
        src = x;  qh = qah;  ql = qal;  qmul = QA_MUL;
        i = b * 256 + threadIdx.x;           if (i >= A16) return;
    } else if (b < 2 * QB_A) {
        src = h;  qh = qah + A16;  ql = qal + A16;  qmul = QA_MUL;
        i = (b - QB_A) * 256 + threadIdx.x;  if (i >= A16) return;
    } else if (b < 2 * QB_A + QB_W) {
        src = wih;  qh = qwh;  ql = qwl;  qmul = QW_MUL;
        i = (b - 2 * QB_A) * 256 + threadIdx.x;        if (i >= W16) return;
    } else {
        src = whh;  qh = qwh + W16;  ql = qwl + W16;  qmul = QW_MUL;
        i = (b - 2 * QB_A - QB_W) * 256 + threadIdx.x; if (i >= W16) return;
    }

    float4 v[4];
    v[0] = src[4 * i];
    v[1] = src[4 * i + 1];
    v[2] = src[4 * i + 2];
    v[3] = src[4 * i + 3];
    union { uint4 u; signed char c[16]; } H, L;
    const float* f = (const float*)v;
    #pragma unroll
    for (int k = 0; k < 16; ++k) {
        int q = __float2int_rn(f[k] * qmul);
        q = max(-16256, min(16256, q));
        int hq = (q + 64) >> 7;
        int lq = q - (hq << 7);
        H.c[k] = (signed char)hq;
        L.c[k] = (signed char)lq;
    }
    qh[i] = H.u;
    ql[i] = L.u;
}

// ---------------- tile loader: K128 chunk, 4 x 16KB regions ----------------
__device__ __forceinline__ void load_chunk(int c, uint32_t stage, int m0, int hb, int tid)
{
    const int ph = c >> 4;
    const int k0 = (c & 15) * BK;
    const signed char* __restrict__ Ah = g_qah[ph];
    const signed char* __restrict__ Al = g_qal[ph];
    const signed char* __restrict__ Wh = g_qwh[ph];
    const signed char* __restrict__ Wl = g_qwl[ph];

    #pragma unroll
    for (int j = 0; j < 2; ++j) {          // A: 128 rows x 8 x 16B = 1024 items
        int idx = tid + j * NTH;
        int r = idx >> 3, cb = idx & 7;
        uint32_t so = swz((uint32_t)(r * ROWB + cb * 16));
        size_t go = (size_t)(m0 + r) * KK + k0 + cb * 16;
        cp16(stage + so, Ah + go);
        cp16(stage + OFF_AL + so, Al + go);
    }
    #pragma unroll
    for (int j = 0; j < 2; ++j) {          // W: 128 rows (4 gates x 32 h)
        int idx = tid + j * NTH;
        int r = idx >> 3, cb = idx & 7;
        uint32_t so = swz((uint32_t)(r * ROWB + cb * 16));
        int wrow = ((r >> 5) << 11) + hb + (r & 31);   // gate*2048 + hb + h
        size_t go = (size_t)wrow * KK + k0 + cb * 16;
        cp16(stage + OFF_WH + so, Wh + go);
        cp16(stage + OFF_WL + so, Wl + go);
    }
}

// ---------------- int8 3-product GEMM + fused LSTM epilogue ----------------
// 512 threads, 3 stages, ONE barrier per chunk.
__global__ __launch_bounds__(NTH, 1)
void lstm_gemm_fused(const float* __restrict__ Cprev,
                     const float* __restrict__ bih,
                     const float* __restrict__ bhh,
                     float* __restrict__ out)
{
    extern __shared__ __align__(1024) char smem[];
    const uint32_t sb = smem_u32(smem);
    const int tid = threadIdx.x;
    const int wid = tid >> 5;
    const int l   = tid & 31;
    const int m0  = blockIdx.y * BM;
    const int hb  = blockIdx.x * 32;
    const int wm  = wid & 3;      // 4 x 32-row slab
    const int wn  = wid >> 2;     // 4 x 32-col slab

    int acc1[2][4][4], acc2[2][4][4];
    #pragma unroll
    for (int mt = 0; mt < 2; ++mt)
        #pragma unroll
        for (int nt = 0; nt < 4; ++nt)
            #pragma unroll
            for (int q = 0; q < 4; ++q) { acc1[mt][nt][q] = 0; acc2[mt][nt][q] = 0; }

    uint32_t swzA[2];
    #pragma unroll
    for (int mt = 0; mt < 2; ++mt) {
        int r = wm * 32 + mt * 16 + (l & 15);
        swzA[mt] = swz((uint32_t)(r * ROWB + (l >> 4) * 16));
    }
    uint32_t swzB[2];
    #pragma unroll
    for (int np = 0; np < 2; ++np) {
        int r = wn * 32 + np * 16 + ((l >> 4) << 3) + (l & 7);
        swzB[np] = swz((uint32_t)(r * ROWB + ((l >> 3) & 1) * 16));
    }

    // prologue: 2 chunks in flight (3rd stage = write/read decouple slot)
    load_chunk(0, sb, m0, hb, tid);
    cp_commit();
    load_chunk(1, sb + STAGE_BYTES, m0, hb, tid);
    cp_commit();

    for (int c = 0; c < NCHUNK; ++c) {
        const uint32_t base = sb + (uint32_t)(c % NSTAGE) * STAGE_BYTES;

        cp_wait<1>();            // chunk c resident (c+1 in flight)
        __syncthreads();         // compute c-1 done by all -> stage (c+2)%3 free

        if (c + 2 < NCHUNK)
            load_chunk(c + 2, sb + (uint32_t)((c + 2) % NSTAGE) * STAGE_BYTES,
                       m0, hb, tid);
        cp_commit();             // flight covered by compute of c and c+1

        #pragma unroll
        for (int ks = 0; ks < 4; ++ks) {
            const uint32_t kx = (uint32_t)ks << 5;
            uint32_t bh[2][4], bl[2][4];
            #pragma unroll
            for (int np = 0; np < 2; ++np) {
                ldsm4(bh[np], base + OFF_WH + (swzB[np] ^ kx));
                ldsm4(bl[np], base + OFF_WL + (swzB[np] ^ kx));
            }
            uint32_t ah[2][4], al[2][4];
            #pragma unroll
            for (int mt = 0; mt < 2; ++mt) {
                ldsm4(ah[mt], base + (swzA[mt] ^ kx));
                ldsm4(al[mt], base + OFF_AL + (swzA[mt] ^ kx));
            }
            #pragma unroll
            for (int mt = 0; mt < 2; ++mt) {
                #pragma unroll
                for (int nt = 0; nt < 4; ++nt)
                    mma_s8(acc1[mt][nt], ah[mt], &bh[nt >> 1][(nt & 1) * 2]);
                #pragma unroll
                for (int nt = 0; nt < 4; ++nt)
                    mma_s8(acc2[mt][nt], ah[mt], &bl[nt >> 1][(nt & 1) * 2]);
                #pragma unroll
                for (int nt = 0; nt < 4; ++nt)
                    mma_s8(acc2[mt][nt], al[mt], &bh[nt >> 1][(nt & 1) * 2]);
            }
        }
    }

    // ---- fused epilogue ----
    __syncthreads();
    float* sg = (float*)smem;              // [128][EPI_STRIDE] f32 gate tile

    const int rb = wm * 32 + (l >> 2);
    const int cb = wn * 32 + 2 * (l & 3);
    #pragma unroll
    for (int mt = 0; mt < 2; ++mt) {
        #pragma unroll
        for (int nt = 0; nt < 4; ++nt) {
            const int r = rb + mt * 16;
            const int cc = cb + nt * 8;
            float g0 = C1_F * fmaf(INV128, (float)acc2[mt][nt][0], (float)acc1[mt][nt][0]);
            float g1 = C1_F * fmaf(INV128, (float)acc2[mt][nt][1], (float)acc1[mt][nt][1]);
            float g2 = C1_F * fmaf(INV128, (float)acc2[mt][nt][2], (float)acc1[mt][nt][2]);
            float g3 = C1_F * fmaf(INV128, (float)acc2[mt][nt][3], (float)acc1[mt][nt][3]);
            sg[r * EPI_STRIDE + cc]           = g0;
            sg[r * EPI_STRIDE + cc + 1]       = g1;
            sg[(r + 8) * EPI_STRIDE + cc]     = g2;
            sg[(r + 8) * EPI_STRIDE + cc + 1] = g3;
        }
    }
    __syncthreads();

    const int hh = (tid & 7) * 4;
    const int H = hb + hh;
    float4 bI, bF, bG, bO;
    {
        float4 a0 = *(const float4*)(bih + H);
        float4 a1 = *(const float4*)(bhh + H);
        bI = make_float4(a0.x + a1.x, a0.y + a1.y, a0.z + a1.z, a0.w + a1.w);
        a0 = *(const float4*)(bih + HH + H);
        a1 = *(const float4*)(bhh + HH + H);
        bF = make_float4(a0.x + a1.x, a0.y + a1.y, a0.z + a1.z, a0.w + a1.w);
        a0 = *(const float4*)(bih + 2 * HH + H);
        a1 = *(const float4*)(bhh + 2 * HH + H);
        bG = make_float4(a0.x + a1.x, a0.y + a1.y, a0.z + a1.z, a0.w + a1.w);
        a0 = *(const float4*)(bih + 3 * HH + H);
        a1 = *(const float4*)(bhh + 3 * HH + H);
        bO = make_float4(a0.x + a1.x, a0.y + a1.y, a0.z + a1.z, a0.w + a1.w);
    }
    const size_t S = (size_t)BB * HH;

    for (int mr = tid >> 3; mr < BM; mr += 64) {
        const float* row = sg + mr * EPI_STRIDE;
        float4 gi = *(const float4*)(row + hh);
        float4 gf = *(const float4*)(row + 32 + hh);
        float4 gg = *(const float4*)(row + 64 + hh);
        float4 go = *(const float4*)(row + 96 + hh);
        const size_t gidx = (size_t)(m0 + mr) * HH + H;
        float4 C = *(const float4*)(Cprev + gidx);

        float4 vh, vC, vf, vi, vg, vo;
        const float* pgi = &gi.x; const float* pgf = &gf.x;
        const float* pgg = &gg.x; const float* pgo = &go.x;
        const float* pbI = &bI.x; const float* pbF = &bF.x;
        const float* pbG = &bG.x; const float* pbO = &bO.x;
        const float* pC = &C.x;
        float* ph = &vh.x; float* pc = &vC.x; float* pf = &vf.x;
        float* pi = &vi.x; float* pg = &vg.x; float* po = &vo.x;
        #pragma unroll
        for (int q = 0; q < 4; ++q) {
            float ig = sigmoidf_(pgi[q] + pbI[q]);
            float fg = sigmoidf_(pgf[q] + pbF[q]);
            float cg = tanhf(pgg[q] + pbG[q]);
            float og = sigmoidf_(pgo[q] + pbO[q]);
            float nC = fg * pC[q] + ig * cg;
            pf[q] = fg; pi[q] = ig; pg[q] = cg; po[q] = og;
            pc[q] = nC;
            ph[q] = og * tanhf(nC);
        }
        *(float4*)(out + gidx)         = vh;
        *(float4*)(out + S + gidx)     = vC;
        *(float4*)(out + 2 * S + gidx) = vf;
        *(float4*)(out + 3 * S + gidx) = vi;
        *(float4*)(out + 4 * S + gidx) = vg;
        *(float4*)(out + 5 * S + gidx) = vo;
    }
}

// ---------------- launch ----------------
extern "C" void kernel_launch(void* const* d_in, const int* in_sizes, int n_in,
                              void* d_out, int out_size)
{
    const float* x     = (const float*)d_in[0];
    const float* hprev = (const float*)d_in[1];
    const float* Cprev = (const float*)d_in[2];
    const float* Wih   = (const float*)d_in[3];
    const float* bih   = (const float*)d_in[4];
    const float* Whh   = (const float*)d_in[5];
    const float* bhh   = (const float*)d_in[6];
    float* out = (float*)d_out;

    signed char *qah, *qal, *qwh, *qwl;
    cudaGetSymbolAddress((void**)&qah, g_qah);
    cudaGetSymbolAddress((void**)&qal, g_qal);
    cudaGetSymbolAddress((void**)&qwh, g_qwh);
    cudaGetSymbolAddress((void**)&qwl, g_qwl);

    static bool attr_set = false;
    if (!attr_set) {
        cudaFuncSetAttribute(lstm_gemm_fused,
                             cudaFuncAttributeMaxDynamicSharedMemorySize, SMEM_TOTAL);
        attr_set = true;
    }

    quant_all<<<2 * QB_A + 2 * QB_W, 256>>>(
        (const float4*)x, (const float4*)hprev,
        (const float4*)Wih, (const float4*)Whh,
        (uint4*)qah, (uint4*)qal, (uint4*)qwh, (uint4*)qwl);

    dim3 grid(FH / BN, BB / BM);   // (64, 16)
    lstm_gemm_fused<<<grid, NTH, SMEM_TOTAL>>>(Cprev, bih, bhh, out);
}

// round 13
// speedup vs baseline: 1.3286x; 1.2724x over previous
#include <cuda_runtime.h>
#include <cuda_fp16.h>
#include <cstdint>
#include <math.h>

// ---------------- problem constants ----------------
#define BB 2048
#define KK 2048
#define HH 2048
#define FH 8192

// ---------------- GEMM config (R10 loop structure, fp16 single product) -----
#define BM 64
#define BN 128             // 4 gates x 32 h
#define BK 128             // fp16 K elems per chunk, two 64-elem sub-blocks
#define NTH 256            // 8 warps: 2 (M) x 4 (N)
#define NCHUNK 32          // 2 phases * (2048/128)
#define ROWB 128           // 64 fp16 per row-block
#define OFF_A1  8192
#define OFF_W0 16384
#define OFF_W1 32768
#define STAGE_BYTES 49152  // A 16K + W 32K
#define NSTAGE 2
#define SMEM_TOTAL (NSTAGE*STAGE_BYTES)   // 96 KB; 2 CTAs/SM = 192 KB
#define EPI_STRIDE 132

// ---------------- scratch ----------------
__device__ __align__(16) __half g_a[2][(size_t)BB*KK];   // x, h (fp16)
__device__ __align__(16) __half g_w[2][(size_t)FH*KK];   // Wih, Whh (fp16)

// ---------------- PTX helpers ----------------
__device__ __forceinline__ uint32_t smem_u32(const void* p) {
    return (uint32_t)__cvta_generic_to_shared(p);
}
__device__ __forceinline__ void cp16(uint32_t s, const void* g) {
    asm volatile("cp.async.cg.shared.global [%0], [%1], 16;"
                 :: "r"(s), "l"(__cvta_generic_to_global(g)) : "memory");
}
__device__ __forceinline__ void cp_commit() {
    asm volatile("cp.async.commit_group;" ::: "memory");
}
template <int N>
__device__ __forceinline__ void cp_wait() {
    asm volatile("cp.async.wait_group %0;" :: "n"(N) : "memory");
}
__device__ __forceinline__ void ldsm4(uint32_t* r, uint32_t a) {
    asm volatile("ldmatrix.sync.aligned.m8n8.x4.shared.b16 {%0,%1,%2,%3}, [%4];"
                 : "=r"(r[0]), "=r"(r[1]), "=r"(r[2]), "=r"(r[3]) : "r"(a));
}
__device__ __forceinline__ void mma16816(float* c, const uint32_t* a, const uint32_t* b) {
    asm volatile(
        "mma.sync.aligned.m16n8k16.row.col.f32.f16.f16.f32 "
        "{%0,%1,%2,%3}, {%4,%5,%6,%7}, {%8,%9}, {%0,%1,%2,%3};"
        : "+f"(c[0]), "+f"(c[1]), "+f"(c[2]), "+f"(c[3])
        : "r"(a[0]), "r"(a[1]), "r"(a[2]), "r"(a[3]), "r"(b[0]), "r"(b[1]));
}
__device__ __forceinline__ uint32_t swz(uint32_t x) {   // SW128
    return x ^ ((x >> 3) & 0x70);
}
__device__ __forceinline__ float sigmoidf_(float v) { return 1.0f / (1.0f + expf(-v)); }

// ---------------- one fused fp32 -> fp16 convert for all four tensors -------
// n8-slot space: x 524288 | h 524288 | Wih 2097152 | Whh 2097152 (uint4 out)
#define CB_A 2048
#define CB_W 8192
__device__ __forceinline__ uint32_t packh2(float a, float b) {
    __half2 p(__float2half_rn(a), __float2half_rn(b));
    return *(uint32_t*)&p;
}
__global__ void convert_all(const float4* __restrict__ x,
                            const float4* __restrict__ h,
                            const float4* __restrict__ wih,
                            const float4* __restrict__ whh,
                            uint4* __restrict__ a16, uint4* __restrict__ w16)
{
    const int b = blockIdx.x;
    const float4* src;
    uint4* dst;
    int i;
    const int A8 = BB * KK / 8;
    const int W8 = FH * KK / 8;

    if (b < CB_A) {
        src = x;   dst = a16;        i = b * 256 + threadIdx.x;
        if (i >= A8) return;
    } else if (b < 2 * CB_A) {
        src = h;   dst = a16 + A8;   i = (b - CB_A) * 256 + threadIdx.x;
        if (i >= A8) return;
    } else if (b < 2 * CB_A + CB_W) {
        src = wih; dst = w16;        i = (b - 2 * CB_A) * 256 + threadIdx.x;
        if (i >= W8) return;
    } else {
        src = whh; dst = w16 + W8;   i = (b - 2 * CB_A - CB_W) * 256 + threadIdx.x;
        if (i >= W8) return;
    }

    float4 v0 = src[2 * i];
    float4 v1 = src[2 * i + 1];
    uint4 o;
    o.x = packh2(v0.x, v0.y);
    o.y = packh2(v0.z, v0.w);
    o.z = packh2(v1.x, v1.y);
    o.w = packh2(v1.z, v1.w);
    dst[i] = o;
}

// ---------------- tile loader: K128 chunk, sub-blocked 128B rows -------------
// stage: [A k0-63 8K][A k64-127 8K][W k0-63 16K][W k64-127 16K]
__device__ __forceinline__ void load_chunk(int c, uint32_t stage, int m0, int hb, int tid)
{
    const int ph = c >> 4;
    const int k0 = (c & 15) * BK;
    const __half* __restrict__ A = g_a[ph];
    const __half* __restrict__ W = g_w[ph];

    #pragma unroll
    for (int j = 0; j < 4; ++j) {          // A: 64 rows x 16 x 16B = 1024 items
        int idx = tid + j * NTH;
        int r = idx >> 4, cb = idx & 15;
        int blk = cb >> 3, w16 = cb & 7;
        uint32_t so = (uint32_t)blk * OFF_A1 + swz((uint32_t)(r * ROWB + w16 * 16));
        size_t go = (size_t)(m0 + r) * KK + k0 + blk * 64 + w16 * 8;
        cp16(stage + so, A + go);
    }
    #pragma unroll
    for (int j = 0; j < 8; ++j) {          // W: 128 rows x 16 x 16B = 2048 items
        int idx = tid + j * NTH;
        int r = idx >> 4, cb = idx & 15;
        int blk = cb >> 3, w16 = cb & 7;
        int wrow = ((r >> 5) << 11) + hb + (r & 31);   // gate*2048 + hb + h
        uint32_t so = OFF_W0 + (uint32_t)blk * 16384 +
                      swz((uint32_t)(r * ROWB + w16 * 16));
        size_t go = (size_t)wrow * KK + k0 + blk * 64 + w16 * 8;
        cp16(stage + so, W + go);
    }
}

// ---------------- single-product fp16 GEMM + fused LSTM epilogue ------------
__global__ __launch_bounds__(NTH, 2)
void lstm_gemm_fused(const float* __restrict__ Cprev,
                     const float* __restrict__ bih,
                     const float* __restrict__ bhh,
                     float* __restrict__ out)
{
    extern __shared__ __align__(1024) char smem[];
    const uint32_t sb = smem_u32(smem);
    const int tid = threadIdx.x;
    const int wid = tid >> 5;
    const int l   = tid & 31;
    const int m0  = blockIdx.y * BM;
    const int hb  = blockIdx.x * 32;
    const int wm  = wid & 1;      // 32-row slab
    const int wn  = wid >> 1;     // 32-col slab

    float acc[2][4][4];
    #pragma unroll
    for (int mt = 0; mt < 2; ++mt)
        #pragma unroll
        for (int nt = 0; nt < 4; ++nt)
            #pragma unroll
            for (int q = 0; q < 4; ++q) acc[mt][nt][q] = 0.0f;

    // k-step within a 64-elem block: +32B applied by XOR (proven R7/R10).
    uint32_t swzA[2];
    #pragma unroll
    for (int mt = 0; mt < 2; ++mt) {
        int r = wm * 32 + mt * 16 + (l & 15);
        swzA[mt] = swz((uint32_t)(r * ROWB + (l >> 4) * 16));
    }
    uint32_t swzB[2];
    #pragma unroll
    for (int np = 0; np < 2; ++np) {
        int r = wn * 32 + np * 16 + ((l >> 4) << 3) + (l & 7);
        swzB[np] = swz((uint32_t)(r * ROWB + ((l >> 3) & 1) * 16));
    }

    load_chunk(0, sb, m0, hb, tid);
    cp_commit();
    load_chunk(1, sb + STAGE_BYTES, m0, hb, tid);
    cp_commit();

    for (int c = 0; c < NCHUNK; ++c) {
        const uint32_t base = sb + (uint32_t)(c & 1) * STAGE_BYTES;

        cp_wait<1>();            // chunk c resident (c+1 in flight)
        __syncthreads();

        #pragma unroll
        for (int ks = 0; ks < 8; ++ks) {
            const uint32_t aBlk = base + (uint32_t)(ks >> 2) * OFF_A1;
            const uint32_t wBlk = base + OFF_W0 + (uint32_t)(ks >> 2) * 16384;
            const uint32_t kx = (uint32_t)(ks & 3) << 5;

            uint32_t bfr[2][4];
            #pragma unroll
            for (int np = 0; np < 2; ++np)
                ldsm4(bfr[np], wBlk + (swzB[np] ^ kx));
            uint32_t afr[2][4];
            #pragma unroll
            for (int mt = 0; mt < 2; ++mt)
                ldsm4(afr[mt], aBlk + (swzA[mt] ^ kx));

            #pragma unroll
            for (int mt = 0; mt < 2; ++mt)
                #pragma unroll
                for (int nt = 0; nt < 4; ++nt)
                    mma16816(acc[mt][nt], afr[mt], &bfr[nt >> 1][(nt & 1) * 2]);
        }

        __syncthreads();
        if (c + NSTAGE < NCHUNK)
            load_chunk(c + NSTAGE, base, m0, hb, tid);
        cp_commit();
    }

    // ---- fused epilogue (identical structure to R10) ----
    __syncthreads();
    float* sg = (float*)smem;              // [64][EPI_STRIDE] f32 gate tile

    const int rb = wm * 32 + (l >> 2);
    const int cb = wn * 32 + 2 * (l & 3);
    #pragma unroll
    for (int mt = 0; mt < 2; ++mt) {
        #pragma unroll
        for (int nt = 0; nt < 4; ++nt) {
            const int r = rb + mt * 16;
            const int cc = cb + nt * 8;
            sg[r * EPI_STRIDE + cc]           = acc[mt][nt][0];
            sg[r * EPI_STRIDE + cc + 1]       = acc[mt][nt][1];
            sg[(r + 8) * EPI_STRIDE + cc]     = acc[mt][nt][2];
            sg[(r + 8) * EPI_STRIDE + cc + 1] = acc[mt][nt][3];
        }
    }
    __syncthreads();

    const int hh = (tid & 7) * 4;
    const int H = hb + hh;
    float4 bI, bF, bG, bO;
    {
        float4 a0 = *(const float4*)(bih + H);
        float4 a1 = *(const float4*)(bhh + H);
        bI = make_float4(a0.x + a1.x, a0.y + a1.y, a0.z + a1.z, a0.w + a1.w);
        a0 = *(const float4*)(bih + HH + H);
        a1 = *(const float4*)(bhh + HH + H);
        bF = make_float4(a0.x + a1.x, a0.y + a1.y, a0.z + a1.z, a0.w + a1.w);
        a0 = *(const float4*)(bih + 2 * HH + H);
        a1 = *(const float4*)(bhh + 2 * HH + H);
        bG = make_float4(a0.x + a1.x, a0.y + a1.y, a0.z + a1.z, a0.w + a1.w);
        a0 = *(const float4*)(bih + 3 * HH + H);
        a1 = *(const float4*)(bhh + 3 * HH + H);
        bO = make_float4(a0.x + a1.x, a0.y + a1.y, a0.z + a1.z, a0.w + a1.w);
    }
    const size_t S = (size_t)BB * HH;

    for (int mr = tid >> 3; mr < BM; mr += 32) {
        const float* row = sg + mr * EPI_STRIDE;
        float4 gi = *(const float4*)(row + hh);
        float4 gf = *(const float4*)(row + 32 + hh);
        float4 gg = *(const float4*)(row + 64 + hh);
        float4 go = *(const float4*)(row + 96 + hh);
        const size_t gidx = (size_t)(m0 + mr) * HH + H;
        float4 C = *(const float4*)(Cprev + gidx);

        float4 vh, vC, vf, vi, vg, vo;
        const float* pgi = &gi.x; const float* pgf = &gf.x;
        const float* pgg = &gg.x; const float* pgo = &go.x;
        const float* pbI = &bI.x; const float* pbF = &bF.x;
        const float* pbG = &bG.x; const float* pbO = &bO.x;
        const float* pC = &C.x;
        float* ph = &vh.x; float* pc = &vC.x; float* pf = &vf.x;
        float* pi = &vi.x; float* pg = &vg.x; float* po = &vo.x;
        #pragma unroll
        for (int q = 0; q < 4; ++q) {
            float ig = sigmoidf_(pgi[q] + pbI[q]);
            float fg = sigmoidf_(pgf[q] + pbF[q]);
            float cg = tanhf(pgg[q] + pbG[q]);
            float og = sigmoidf_(pgo[q] + pbO[q]);
            float nC = fg * pC[q] + ig * cg;
            pf[q] = fg; pi[q] = ig; pg[q] = cg; po[q] = og;
            pc[q] = nC;
            ph[q] = og * tanhf(nC);
        }
        *(float4*)(out + gidx)         = vh;
        *(float4*)(out + S + gidx)     = vC;
        *(float4*)(out + 2 * S + gidx) = vf;
        *(float4*)(out + 3 * S + gidx) = vi;
        *(float4*)(out + 4 * S + gidx) = vg;
        *(float4*)(out + 5 * S + gidx) = vo;
    }
}

// ---------------- launch ----------------
extern "C" void kernel_launch(void* const* d_in, const int* in_sizes, int n_in,
                              void* d_out, int out_size)
{
    const float* x     = (const float*)d_in[0];
    const float* hprev = (const float*)d_in[1];
    const float* Cprev = (const float*)d_in[2];
    const float* Wih   = (const float*)d_in[3];
    const float* bih   = (const float*)d_in[4];
    const float* Whh   = (const float*)d_in[5];
    const float* bhh   = (const float*)d_in[6];
    float* out = (float*)d_out;

    __half *a16, *w16;
    cudaGetSymbolAddress((void**)&a16, g_a);
    cudaGetSymbolAddress((void**)&w16, g_w);

    static bool attr_set = false;
    if (!attr_set) {
        cudaFuncSetAttribute(lstm_gemm_fused,
                             cudaFuncAttributeMaxDynamicSharedMemorySize, SMEM_TOTAL);
        attr_set = true;
    }

    convert_all<<<2 * CB_A + 2 * CB_W, 256>>>(
        (const float4*)x, (const float4*)hprev,
        (const float4*)Wih, (const float4*)Whh,
        (uint4*)a16, (uint4*)w16);

    dim3 grid(FH / BN, BB / BM);   // (64, 32)
    lstm_gemm_fused<<<grid, NTH, SMEM_TOTAL>>>(Cprev, bih, bhh, out);
}

// round 14
// speedup vs baseline: 1.3328x; 1.0032x over previous
#include <cuda_runtime.h>
#include <cuda_fp16.h>
#include <cstdint>
#include <math.h>

// ---------------- problem constants ----------------
#define BB 2048
#define KK 2048
#define HH 2048
#define FH 8192

// ---------------- GEMM config: fp16 single product, wide warp tiles ---------
#define BM 64
#define BN 128             // 4 gates x 32 h
#define BK 128             // two 64-elem sub-blocks (128B rows)
#define NTH 128            // 4 warps: 2 (M, m32) x 2 (N, n64)
#define NCHUNK 32          // 2 phases * (2048/128)
#define ROWB 128
#define OFF_A1  8192
#define OFF_W0 16384
#define STAGE_BYTES 49152  // A 16K + W 32K
#define NSTAGE 2
#define SMEM_TOTAL (NSTAGE*STAGE_BYTES)   // 96 KB; 2 CTAs/SM
#define EPI_STRIDE 132

// ---------------- scratch ----------------
__device__ __align__(16) __half g_a[2][(size_t)BB*KK];   // x, h (fp16)
__device__ __align__(16) __half g_w[2][(size_t)FH*KK];   // Wih, Whh (fp16)

// ---------------- PTX helpers ----------------
__device__ __forceinline__ uint32_t smem_u32(const void* p) {
    return (uint32_t)__cvta_generic_to_shared(p);
}
__device__ __forceinline__ void cp16(uint32_t s, const void* g) {
    asm volatile("cp.async.cg.shared.global [%0], [%1], 16;"
                 :: "r"(s), "l"(__cvta_generic_to_global(g)) : "memory");
}
__device__ __forceinline__ void cp_commit() {
    asm volatile("cp.async.commit_group;" ::: "memory");
}
template <int N>
__device__ __forceinline__ void cp_wait() {
    asm volatile("cp.async.wait_group %0;" :: "n"(N) : "memory");
}
__device__ __forceinline__ void ldsm4(uint32_t* r, uint32_t a) {
    asm volatile("ldmatrix.sync.aligned.m8n8.x4.shared.b16 {%0,%1,%2,%3}, [%4];"
                 : "=r"(r[0]), "=r"(r[1]), "=r"(r[2]), "=r"(r[3]) : "r"(a));
}
__device__ __forceinline__ void mma16816(float* c, const uint32_t* a, const uint32_t* b) {
    asm volatile(
        "mma.sync.aligned.m16n8k16.row.col.f32.f16.f16.f32 "
        "{%0,%1,%2,%3}, {%4,%5,%6,%7}, {%8,%9}, {%0,%1,%2,%3};"
        : "+f"(c[0]), "+f"(c[1]), "+f"(c[2]), "+f"(c[3])
        : "r"(a[0]), "r"(a[1]), "r"(a[2]), "r"(a[3]), "r"(b[0]), "r"(b[1]));
}
__device__ __forceinline__ uint32_t swz(uint32_t x) {   // SW128
    return x ^ ((x >> 3) & 0x70);
}
__device__ __forceinline__ float sigmoidf_(float v) { return 1.0f / (1.0f + expf(-v)); }

// ---------------- one fused fp32 -> fp16 convert for all four tensors -------
#define CB_A 2048
#define CB_W 8192
__device__ __forceinline__ uint32_t packh2(float a, float b) {
    __half2 p(__float2half_rn(a), __float2half_rn(b));
    return *(uint32_t*)&p;
}
__global__ void convert_all(const float4* __restrict__ x,
                            const float4* __restrict__ h,
                            const float4* __restrict__ wih,
                            const float4* __restrict__ whh,
                            uint4* __restrict__ a16, uint4* __restrict__ w16)
{
    const int b = blockIdx.x;
    const float4* src;
    uint4* dst;
    int i;
    const int A8 = BB * KK / 8;
    const int W8 = FH * KK / 8;

    if (b < CB_A) {
        src = x;   dst = a16;        i = b * 256 + threadIdx.x;
        if (i >= A8) return;
    } else if (b < 2 * CB_A) {
        src = h;   dst = a16 + A8;   i = (b - CB_A) * 256 + threadIdx.x;
        if (i >= A8) return;
    } else if (b < 2 * CB_A + CB_W) {
        src = wih; dst = w16;        i = (b - 2 * CB_A) * 256 + threadIdx.x;
        if (i >= W8) return;
    } else {
        src = whh; dst = w16 + W8;   i = (b - 2 * CB_A - CB_W) * 256 + threadIdx.x;
        if (i >= W8) return;
    }

    float4 v0 = src[2 * i];
    float4 v1 = src[2 * i + 1];
    uint4 o;
    o.x = packh2(v0.x, v0.y);
    o.y = packh2(v0.z, v0.w);
    o.z = packh2(v1.x, v1.y);
    o.w = packh2(v1.z, v1.w);
    dst[i] = o;
}

// ---------------- tile loader: K128 chunk, sub-blocked 128B rows -------------
// stage: [A k0-63 8K][A k64-127 8K][W k0-63 16K][W k64-127 16K]
__device__ __forceinline__ void load_chunk(int c, uint32_t stage, int m0, int hb, int tid)
{
    const int ph = c >> 4;
    const int k0 = (c & 15) * BK;
    const __half* __restrict__ A = g_a[ph];
    const __half* __restrict__ W = g_w[ph];

    #pragma unroll
    for (int j = 0; j < 8; ++j) {          // A: 64 rows x 16 x 16B = 1024 items
        int idx = tid + j * NTH;
        int r = idx >> 4, cb = idx & 15;
        int blk = cb >> 3, w16 = cb & 7;
        uint32_t so = (uint32_t)blk * OFF_A1 + swz((uint32_t)(r * ROWB + w16 * 16));
        size_t go = (size_t)(m0 + r) * KK + k0 + blk * 64 + w16 * 8;
        cp16(stage + so, A + go);
    }
    #pragma unroll
    for (int j = 0; j < 16; ++j) {         // W: 128 rows x 16 x 16B = 2048 items
        int idx = tid + j * NTH;
        int r = idx >> 4, cb = idx & 15;
        int blk = cb >> 3, w16 = cb & 7;
        int wrow = ((r >> 5) << 11) + hb + (r & 31);   // gate*2048 + hb + h
        uint32_t so = OFF_W0 + (uint32_t)blk * 16384 +
                      swz((uint32_t)(r * ROWB + w16 * 16));
        size_t go = (size_t)wrow * KK + k0 + blk * 64 + w16 * 8;
        cp16(stage + so, W + go);
    }
}

// ---------------- single-product fp16 GEMM + fused LSTM epilogue ------------
// 4 warps, warp tile m32 x n64: 6 ldsm per 16 MMAs (187B smem/MMA).
__global__ __launch_bounds__(NTH, 2)
void lstm_gemm_fused(const float* __restrict__ Cprev,
                     const float* __restrict__ bih,
                     const float* __restrict__ bhh,
                     float* __restrict__ out)
{
    extern __shared__ __align__(1024) char smem[];
    const uint32_t sb = smem_u32(smem);
    const int tid = threadIdx.x;
    const int wid = tid >> 5;
    const int l   = tid & 31;
    const int m0  = blockIdx.y * BM;
    const int hb  = blockIdx.x * 32;
    const int wm  = wid & 1;      // 32-row slab
    const int wn  = wid >> 1;     // 64-col slab

    float acc[2][8][4];
    #pragma unroll
    for (int mt = 0; mt < 2; ++mt)
        #pragma unroll
        for (int nt = 0; nt < 8; ++nt)
            #pragma unroll
            for (int q = 0; q < 4; ++q) acc[mt][nt][q] = 0.0f;

    uint32_t swzA[2];
    #pragma unroll
    for (int mt = 0; mt < 2; ++mt) {
        int r = wm * 32 + mt * 16 + (l & 15);
        swzA[mt] = swz((uint32_t)(r * ROWB + (l >> 4) * 16));
    }
    uint32_t swzB[4];
    #pragma unroll
    for (int np = 0; np < 4; ++np) {
        int r = wn * 64 + np * 16 + ((l >> 4) << 3) + (l & 7);
        swzB[np] = swz((uint32_t)(r * ROWB + ((l >> 3) & 1) * 16));
    }

    load_chunk(0, sb, m0, hb, tid);
    cp_commit();
    load_chunk(1, sb + STAGE_BYTES, m0, hb, tid);
    cp_commit();

    for (int c = 0; c < NCHUNK; ++c) {
        const uint32_t base = sb + (uint32_t)(c & 1) * STAGE_BYTES;

        cp_wait<1>();
        __syncthreads();

        #pragma unroll
        for (int ks = 0; ks < 8; ++ks) {
            const uint32_t aBlk = base + (uint32_t)(ks >> 2) * OFF_A1;
            const uint32_t wBlk = base + OFF_W0 + (uint32_t)(ks >> 2) * 16384;
            const uint32_t kx = (uint32_t)(ks & 3) << 5;

            uint32_t bfr[4][4];
            #pragma unroll
            for (int np = 0; np < 4; ++np)
                ldsm4(bfr[np], wBlk + (swzB[np] ^ kx));
            uint32_t afr[2][4];
            #pragma unroll
            for (int mt = 0; mt < 2; ++mt)
                ldsm4(afr[mt], aBlk + (swzA[mt] ^ kx));

            #pragma unroll
            for (int mt = 0; mt < 2; ++mt)
                #pragma unroll
                for (int nt = 0; nt < 8; ++nt)
                    mma16816(acc[mt][nt], afr[mt], &bfr[nt >> 1][(nt & 1) * 2]);
        }

        __syncthreads();
        if (c + NSTAGE < NCHUNK)
            load_chunk(c + NSTAGE, base, m0, hb, tid);
        cp_commit();
    }

    // ---- fused epilogue ----
    __syncthreads();
    float* sg = (float*)smem;              // [64][EPI_STRIDE] f32 gate tile

    const int rb = wm * 32 + (l >> 2);
    const int cb = wn * 64 + 2 * (l & 3);
    #pragma unroll
    for (int mt = 0; mt < 2; ++mt) {
        #pragma unroll
        for (int nt = 0; nt < 8; ++nt) {
            const int r = rb + mt * 16;
            const int cc = cb + nt * 8;
            sg[r * EPI_STRIDE + cc]           = acc[mt][nt][0];
            sg[r * EPI_STRIDE + cc + 1]       = acc[mt][nt][1];
            sg[(r + 8) * EPI_STRIDE + cc]     = acc[mt][nt][2];
            sg[(r + 8) * EPI_STRIDE + cc + 1] = acc[mt][nt][3];
        }
    }
    __syncthreads();

    const int hh = (tid & 7) * 4;
    const int H = hb + hh;
    float4 bI, bF, bG, bO;
    {
        float4 a0 = *(const float4*)(bih + H);
        float4 a1 = *(const float4*)(bhh + H);
        bI = make_float4(a0.x + a1.x, a0.y + a1.y, a0.z + a1.z, a0.w + a1.w);
        a0 = *(const float4*)(bih + HH + H);
        a1 = *(const float4*)(bhh + HH + H);
        bF = make_float4(a0.x + a1.x, a0.y + a1.y, a0.z + a1.z, a0.w + a1.w);
        a0 = *(const float4*)(bih + 2 * HH + H);
        a1 = *(const float4*)(bhh + 2 * HH + H);
        bG = make_float4(a0.x + a1.x, a0.y + a1.y, a0.z + a1.z, a0.w + a1.w);
        a0 = *(const float4*)(bih + 3 * HH + H);
        a1 = *(const float4*)(bhh + 3 * HH + H);
        bO = make_float4(a0.x + a1.x, a0.y + a1.y, a0.z + a1.z, a0.w + a1.w);
    }
    const size_t S = (size_t)BB * HH;

    for (int mr = tid >> 3; mr < BM; mr += 16) {
        const float* row = sg + mr * EPI_STRIDE;
        float4 gi = *(const float4*)(row + hh);
        float4 gf = *(const float4*)(row + 32 + hh);
        float4 gg = *(const float4*)(row + 64 + hh);
        float4 go = *(const float4*)(row + 96 + hh);
        const size_t gidx = (size_t)(m0 + mr) * HH + H;
        float4 C = *(const float4*)(Cprev + gidx);

        float4 vh, vC, vf, vi, vg, vo;
        const float* pgi = &gi.x; const float* pgf = &gf.x;
        const float* pgg = &gg.x; const float* pgo = &go.x;
        const float* pbI = &bI.x; const float* pbF = &bF.x;
        const float* pbG = &bG.x; const float* pbO = &bO.x;
        const float* pC = &C.x;
        float* ph = &vh.x; float* pc = &vC.x; float* pf = &vf.x;
        float* pi = &vi.x; float* pg = &vg.x; float* po = &vo.x;
        #pragma unroll
        for (int q = 0; q < 4; ++q) {
            float ig = sigmoidf_(pgi[q] + pbI[q]);
            float fg = sigmoidf_(pgf[q] + pbF[q]);
            float cg = tanhf(pgg[q] + pbG[q]);
            float og = sigmoidf_(pgo[q] + pbO[q]);
            float nC = fg * pC[q] + ig * cg;
            pf[q] = fg; pi[q] = ig; pg[q] = cg; po[q] = og;
            pc[q] = nC;
            ph[q] = og * tanhf(nC);
        }
        *(float4*)(out + gidx)         = vh;
        *(float4*)(out + S + gidx)     = vC;
        *(float4*)(out + 2 * S + gidx) = vf;
        *(float4*)(out + 3 * S + gidx) = vi;
        *(float4*)(out + 4 * S + gidx) = vg;
        *(float4*)(out + 5 * S + gidx) = vo;
    }
}

// ---------------- launch ----------------
extern "C" void kernel_launch(void* const* d_in, const int* in_sizes, int n_in,
                              void* d_out, int out_size)
{
    const float* x     = (const float*)d_in[0];
    const float* hprev = (const float*)d_in[1];
    const float* Cprev = (const float*)d_in[2];
    const float* Wih   = (const float*)d_in[3];
    const float* bih   = (const float*)d_in[4];
    const float* Whh   = (const float*)d_in[5];
    const float* bhh   = (const float*)d_in[6];
    float* out = (float*)d_out;

    __half *a16, *w16;
    cudaGetSymbolAddress((void**)&a16, g_a);
    cudaGetSymbolAddress((void**)&w16, g_w);

    static bool attr_set = false;
    if (!attr_set) {
        cudaFuncSetAttribute(lstm_gemm_fused,
                             cudaFuncAttributeMaxDynamicSharedMemorySize, SMEM_TOTAL);
        attr_set = true;
    }

    convert_all<<<2 * CB_A + 2 * CB_W, 256>>>(
        (const float4*)x, (const float4*)hprev,
        (const float4*)Wih, (const float4*)Whh,
        (uint4*)a16, (uint4*)w16);

    dim3 grid(FH / BN, BB / BM);   // (64, 32)
    lstm_gemm_fused<<<grid, NTH, SMEM_TOTAL>>>(Cprev, bih, bhh, out);
}